// round 5
// baseline (speedup 1.0000x reference)
#include <cuda_runtime.h>

#define NTAG  9
#define SEQ   512
#define BATCH 4096
#define NCTA  342                 // 4 warps/CTA * 3 seqs/warp-group * 342 >= 4096

// ---- device scratch (globals: allocation-free) ----
__device__ int    g_len[BATCH];
__device__ int    g_hist[SEQ + 1];     // BSS zero-init; re-zeroed by prefix kernel each call
__device__ int    g_binoff[SEQ + 1];
__device__ int    g_perm[BATCH];
__device__ double g_pacc[NCTA];
__device__ int    g_pchars[NCTA];

// ============ 1) lengths + histogram (warp per sequence) ============
__global__ void __launch_bounds__(128) crf_len_hist(const int* __restrict__ mask)
{
    const int lane = threadIdx.x & 31;
    const int seq  = blockIdx.x * 4 + (threadIdx.x >> 5);
    const int4* m4 = reinterpret_cast<const int4*>(mask + (size_t)seq * SEQ);
    int s = 0;
#pragma unroll
    for (int k = 0; k < 4; k++) {
        int4 v = m4[lane + 32 * k];
        s += v.x + v.y + v.z + v.w;
    }
#pragma unroll
    for (int o = 16; o; o >>= 1) s += __shfl_xor_sync(0xffffffffu, s, o);
    if (lane == 0) {
        g_len[seq] = s;
        atomicAdd(&g_hist[s], 1);
    }
}

// ============ 2) exclusive prefix over hist -> binoff; re-zero hist ============
__global__ void __launch_bounds__(512) crf_prefix()
{
    __shared__ int a[512], b[512];
    const int tid = threadIdx.x;
    a[tid] = g_hist[tid];            // lengths 0..511 (hist[512] handled implicitly)
    __syncthreads();
    int* src = a; int* dst = b;
#pragma unroll
    for (int off = 1; off < 512; off <<= 1) {
        dst[tid] = (tid >= off) ? src[tid] + src[tid - off] : src[tid];
        __syncthreads();
        int* t = src; src = dst; dst = t;
    }
    // inclusive scan of hist[0..511] is in src; binoff[len] = incl[len-1]
    g_binoff[tid + 1] = src[tid];
    if (tid == 0) g_binoff[0] = 0;
    // re-zero hist for the next launch (keeps every call identical)
    g_hist[tid] = 0;
    if (tid == 0) g_hist[512] = 0;
}

// ============ 3) scatter: counting-sort permutation by length ============
__global__ void __launch_bounds__(128) crf_scatter()
{
    const int bseq = blockIdx.x * 128 + threadIdx.x;   // 32 CTAs -> 4096
    const int L    = g_len[bseq];
    const int slot = atomicAdd(&g_binoff[L], 1);
    g_perm[slot] = bseq;
}

// ============ 4) main scan: 3 seqs/warp, 9 lanes/seq, smem broadcast ============
__global__ void __launch_bounds__(128) crf_scan(
    const float* __restrict__ bert,  // [B, S, 9] f32
    const int* __restrict__ tags,    // [B, S] i32
    const float* __restrict__ trans) // [11, 11] f32
{
    __shared__ float  sT[121];
    __shared__ float4 sW[4][2][4][3];   // [warp][parity][group(+pad)][12 floats]
    __shared__ double sAcc;
    __shared__ int    sChars;

    const int tid = threadIdx.x;
    if (tid < 121) sT[tid] = trans[tid];
    if (tid == 0) { sAcc = 0.0; sChars = 0; }
    __syncthreads();

    const int lane  = tid & 31;
    const int wid   = tid >> 5;
    const int g     = lane / 9;          // 0..2 active, 3 = idle lanes 27-31
    const int j     = lane - g * 9;      // tag owned by this lane
    const int gbase = g * 9;

    // strided warp->slot map: CTA c hosts warps {c, c+342, c+684, c+1026}
    const int  gw    = wid * NCTA + blockIdx.x;
    const int  slot  = 3 * gw + g;
    const bool valid = (g < 3) && (slot < BATCH);
    const int  seq   = valid ? g_perm[slot] : 0;
    const int  L     = valid ? g_len[seq] : 0;

    const float* em = bert + (size_t)seq * (SEQ * NTAG);
    const int*   tg = tags + (size_t)seq * SEQ;

    // E column for this lane + end factor
    float E[NTAG];
#pragma unroll
    for (int i = 0; i < NTAG; i++) E[i] = __expf(sT[i * 11 + j]);
    const float Eend = __expf(sT[j * 11 + 10]);

    int maxL = L;
#pragma unroll
    for (int o = 16; o; o >>= 1) maxL = max(maxL, __shfl_xor_sync(0xffffffffu, maxL, o));

    // ---- t = 0 ----
    const float em0  = __ldg(em + j);
    float W    = __expf(sT[99 + j] + em0);       // prob-domain alpha0
    int   eAcc = 0;
    const int tag0 = __ldg(tg);
    float racc   = (tag0 == j) ? em0 : 0.0f;     // per-lane emit accumulation
    float rtrans = (j == 0) ? sT[99 + tag0] : 0.0f;
    int   prev   = tag0;

    // seed buffer parity 1 for iteration t=1
    reinterpret_cast<float*>(&sW[wid][1][g][0])[j] = W;

    // prefetch t = 1
    float emv  = __ldg(em + NTAG + j);
    int   tagc = __ldg(tg + 1);

#pragma unroll 4
    for (int t = 1; t < maxL; ++t) {
        __syncwarp();
        const float* wb = reinterpret_cast<const float*>(&sW[wid][t & 1][g][0]);
        const float4 wa = reinterpret_cast<const float4*>(wb)[0];
        const float4 wc = reinterpret_cast<const float4*>(wb)[1];
        const float  w8 = wb[8];

        // prefetch t+1 (off the alpha chain)
        const int   tn       = min(t + 1, SEQ - 1);
        const float em_next  = __ldg(em + tn * NTAG + j);
        const int   tag_next = __ldg(tg + tn);

        // matvec: acc_j = sum_i W_i * E[i][j]
        float acc = wa.x * E[0];
        acc = fmaf(wa.y, E[1], acc);
        acc = fmaf(wa.z, E[2], acc);
        acc = fmaf(wa.w, E[3], acc);
        acc = fmaf(wc.x, E[4], acc);
        acc = fmaf(wc.y, E[5], acc);
        acc = fmaf(wc.z, E[6], acc);
        acc = fmaf(wc.w, E[7], acc);
        acc = fmaf(w8,   E[8], acc);

        const float X   = __expf(emv);
        const bool  act = (t < L);

        // exact power-of-2 rescale every 4 steps (group-uniform)
        if ((t & 3) == 0) {
            float mx = fmaxf(fmaxf(fmaxf(wa.x, wa.y), fmaxf(wa.z, wa.w)),
                             fmaxf(fmaxf(wc.x, wc.y), fmaxf(wc.z, fmaxf(wc.w, w8))));
            const int e = ((__float_as_int(mx) >> 23) & 255) - 127;
            acc *= __int_as_float((127 - e) << 23);
            if (act) eAcc += e;
        }

        const float Wn = acc * X;
        if (act) {
            W = Wn;
            if (tagc == j) racc += emv;                    // emit gather in-register
            if (j == 0) { rtrans += sT[prev * 11 + tagc]; prev = tagc; }
        }
        reinterpret_cast<float*>(&sW[wid][(t + 1) & 1][g][0])[j] = W;

        emv  = em_next;
        tagc = tag_next;
    }

    // ---- termination: group reductions (one-shot shfl is fine here) ----
    const float v = W * Eend;
    float sv = 0.0f, sr = 0.0f;
#pragma unroll
    for (int i = 0; i < NTAG; i++) {
        sv += __shfl_sync(0xffffffffu, v,    (gbase + i) & 31);
        sr += __shfl_sync(0xffffffffu, racc, (gbase + i) & 31);
    }

    if (j == 0 && valid) {
        const float real = rtrans + sr + sT[prev * 11 + 10];
        const double total = (double)eAcc * 0.6931471805599453 + (double)__logf(sv);
        atomicAdd(&sAcc, total - (double)real);
        atomicAdd(&sChars, L);
    }
    __syncthreads();
    if (tid == 0) {
        g_pacc[blockIdx.x]   = sAcc;
        g_pchars[blockIdx.x] = sChars;
    }
}

// ============ 5) final reduction ============
__global__ void __launch_bounds__(128) crf_fin(float* out)
{
    __shared__ double    sa[128];
    __shared__ long long sc[128];
    const int tid = threadIdx.x;
    double a = 0.0; long long c = 0;
    for (int i = tid; i < NCTA; i += 128) {
        a += g_pacc[i];
        c += (long long)g_pchars[i];
    }
    sa[tid] = a; sc[tid] = c;
    __syncthreads();
    for (int o = 64; o; o >>= 1) {
        if (tid < o) { sa[tid] += sa[tid + o]; sc[tid] += sc[tid + o]; }
        __syncthreads();
    }
    if (tid == 0) out[0] = (float)(sa[0] / (double)sc[0]);
}

extern "C" void kernel_launch(void* const* d_in, const int* in_sizes, int n_in,
                              void* d_out, int out_size)
{
    const float* bert  = (const float*)d_in[0];
    const int*   mask  = (const int*)d_in[1];
    const int*   tags  = (const int*)d_in[2];
    const float* trans = (const float*)d_in[3];
    float* out = (float*)d_out;

    crf_len_hist<<<BATCH / 4, 128>>>(mask);
    crf_prefix<<<1, 512>>>();
    crf_scatter<<<BATCH / 128, 128>>>();
    crf_scan<<<NCTA, 128>>>(bert, tags, trans);
    crf_fin<<<1, 128>>>(out);
}